// round 14
// baseline (speedup 1.0000x reference)
#include <cuda_runtime.h>
#include <cuda_bf16.h>
#include <math.h>

#define PN 256      // paths
#define LN 64       // max length
#define ID 512      // input dim
#define HD 1024     // hidden
#define G4 4096     // 4*HD
#define ASTR 40     // A smem row stride for gemm_xw (bf16 elems)
#define BSTR 136    // B smem row stride (bf16 elems), conflict-free for ldmatrix(.trans)

// gemm_step dynamic smem: double-buffered A(64x136) + B(128x136), bf16
#define STEP_ASZ (64 * 136)
#define STEP_BSZ (128 * 136)
#define SMEM_STEP ((2 * STEP_ASZ + 2 * STEP_BSZ) * 2)

// ---------------- scratch (__device__ globals) ----------------
// Interleaved gate layout: column n = 4*j + g, g in {i,f,g,o}
__device__ __align__(16) unsigned short g_Whb[HD * G4];  // W_hh bf16 k-major interleaved (8MB)
__device__ __align__(16) unsigned short g_Wib[ID * G4];  // W_ih bf16 k-major interleaved (4MB)
__device__ float    g_biasI[G4];                          // (b_ih+b_hh) interleaved
__device__ float    g_xw[(long)LN * PN * G4];             // x_t@W_ih^T + b (256MB)
__device__ __align__(16) unsigned short g_hbf[2][PN * HD]; // h bf16, double-buffered
__device__ float    g_c[PN * HD];
__device__ float    g_fh[PN * HD];                        // final hidden (fp32, for head)
__device__ unsigned g_WvT[HD * HD];                       // W_v k-major tf32
__device__ unsigned g_WoT[HD * HD];                       // W_out k-major tf32
__device__ float    g_v[PN * HD];
__device__ float    g_attn[PN * HD];
__device__ float    g_pool[HD];

// ---------------- helpers ----------------
__device__ __forceinline__ unsigned f2tf(float x) {
    unsigned r;
    asm("cvt.rna.tf32.f32 %0, %1;" : "=r"(r) : "f"(x));
    return r;
}
__device__ __forceinline__ unsigned short btous(float x) {
    return __bfloat16_as_ushort(__float2bfloat16_rn(x));
}
__device__ __forceinline__ float sigf(float x) { return 1.0f / (1.0f + expf(-x)); }

__device__ __forceinline__ void mma_tf32(float c[4],
                                         unsigned a0, unsigned a1, unsigned a2, unsigned a3,
                                         unsigned b0, unsigned b1) {
    asm volatile(
        "mma.sync.aligned.m16n8k8.row.col.f32.tf32.tf32.f32 "
        "{%0,%1,%2,%3},{%4,%5,%6,%7},{%8,%9},{%0,%1,%2,%3};"
        : "+f"(c[0]), "+f"(c[1]), "+f"(c[2]), "+f"(c[3])
        : "r"(a0), "r"(a1), "r"(a2), "r"(a3), "r"(b0), "r"(b1));
}

__device__ __forceinline__ void mma_bf16(float c[4], const unsigned a[4],
                                         unsigned b0, unsigned b1) {
    asm volatile(
        "mma.sync.aligned.m16n8k16.row.col.f32.bf16.bf16.f32 "
        "{%0,%1,%2,%3},{%4,%5,%6,%7},{%8,%9},{%0,%1,%2,%3};"
        : "+f"(c[0]), "+f"(c[1]), "+f"(c[2]), "+f"(c[3])
        : "r"(a[0]), "r"(a[1]), "r"(a[2]), "r"(a[3]), "r"(b0), "r"(b1));
}

__device__ __forceinline__ void ldsm_x4(unsigned r[4], const void* p) {
    unsigned a = (unsigned)__cvta_generic_to_shared(p);
    asm volatile("ldmatrix.sync.aligned.m8n8.x4.shared.b16 {%0,%1,%2,%3}, [%4];"
        : "=r"(r[0]), "=r"(r[1]), "=r"(r[2]), "=r"(r[3]) : "r"(a));
}
__device__ __forceinline__ void ldsm_x4t(unsigned r[4], const void* p) {
    unsigned a = (unsigned)__cvta_generic_to_shared(p);
    asm volatile("ldmatrix.sync.aligned.m8n8.x4.trans.shared.b16 {%0,%1,%2,%3}, [%4];"
        : "=r"(r[0]), "=r"(r[1]), "=r"(r[2]), "=r"(r[3]) : "r"(a));
}

// ---------------- prep ----------------
__global__ void prep_w(const float* __restrict__ Wih, const float* __restrict__ Whh,
                       const float* __restrict__ bih, const float* __restrict__ bhh) {
    const int total = (ID + HD) * G4 + G4;
    for (int e = blockIdx.x * blockDim.x + threadIdx.x; e < total; e += gridDim.x * blockDim.x) {
        if (e < ID * G4) {
            int k = e >> 12, n = e & 4095;
            int j = n >> 2, g = n & 3;
            g_Wib[e] = btous(Wih[(g * HD + j) * ID + k]);
        } else if (e < (ID + HD) * G4) {
            int e2 = e - ID * G4;
            int k = e2 >> 12, n = e2 & 4095;
            int j = n >> 2, g = n & 3;
            g_Whb[e2] = btous(Whh[(g * HD + j) * HD + k]);
        } else {
            int n = e - (ID + HD) * G4;
            int j = n >> 2, g = n & 3;
            g_biasI[n] = bih[g * HD + j] + bhh[g * HD + j];
        }
    }
}

__global__ void prep_rest(const float* __restrict__ Win, const float* __restrict__ Wout) {
    const int HH = HD * HD;
    const int total = 2 * HH + 2 * PN * HD;
    for (int e = blockIdx.x * blockDim.x + threadIdx.x; e < total; e += gridDim.x * blockDim.x) {
        if (e < HH) {
            int k = e >> 10, n = e & 1023;
            g_WvT[e] = f2tf(Win[(2 * HD + n) * HD + k]);
        } else if (e < 2 * HH) {
            int e2 = e - HH;
            int k = e2 >> 10, n = e2 & 1023;
            g_WoT[e2] = f2tf(Wout[n * HD + k]);
        } else {
            int i = e - 2 * HH;
            if (i < PN * HD) g_hbf[0][i] = 0; else g_c[i - PN * HD] = 0.0f;
        }
    }
}

// ---------------- xw precompute GEMM (bf16, unchanged from R13) ----------------
__global__ __launch_bounds__(512) void gemm_xw(const float* __restrict__ emb,
                                               const int* __restrict__ paths) {
    __shared__ __align__(16) unsigned short sA[2][64 * ASTR];
    __shared__ __align__(16) unsigned short sB[2][32 * BSTR];

    const int tid = threadIdx.x;
    const int warp = tid >> 5, lane = tid & 31;
    const int gid = lane >> 2, tig = lane & 3;
    const int wy = warp >> 2, wx = warp & 3;
    const int m0 = blockIdx.y * 64, n0 = blockIdx.x * 128;
    const int tt = m0 >> 8, p0 = m0 & 255;

    const int arow = tid >> 3, ac4 = (tid & 7) * 4;
    const int brow = tid >> 4, bcol = (tid & 15) * 8;

    const long abase = (long)paths[(p0 + arow) * LN + tt] * ID + ac4;

    const int aoff = (wy * 16 + (lane & 15)) * ASTR + (lane >> 4) * 8;
    const int boff = (lane & 15) * BSTR + wx * 32 + (lane >> 4) * 8;

    float4 pa = *(const float4*)(emb + abase);
    uint4  pb = *(const uint4*)(g_Wib + (long)brow * G4 + n0 + bcol);

    {
        unsigned lo = btous(pa.x) | ((unsigned)btous(pa.y) << 16);
        unsigned hi = btous(pa.z) | ((unsigned)btous(pa.w) << 16);
        *(uint2*)&sA[0][arow * ASTR + ac4] = make_uint2(lo, hi);
        *(uint4*)&sB[0][brow * BSTR + bcol] = pb;
    }
    __syncthreads();

    float acc[4][4] = {};

    for (int kt = 0; kt < ID / 32; ++kt) {
        const int cur = kt & 1;
        if (kt < ID / 32 - 1) {
            const int kb = (kt + 1) * 32;
            pa = *(const float4*)(emb + abase + kb);
            pb = *(const uint4*)(g_Wib + (long)(kb + brow) * G4 + n0 + bcol);
        }

        #pragma unroll
        for (int ks = 0; ks < 2; ++ks) {
            unsigned a[4], bt0[4], bt1[4];
            ldsm_x4 (a,   &sA[cur][aoff + ks * 16]);
            ldsm_x4t(bt0, &sB[cur][ks * 16 * BSTR + boff]);
            ldsm_x4t(bt1, &sB[cur][ks * 16 * BSTR + boff + 16]);
            mma_bf16(acc[0], a, bt0[0], bt0[1]);
            mma_bf16(acc[1], a, bt0[2], bt0[3]);
            mma_bf16(acc[2], a, bt1[0], bt1[1]);
            mma_bf16(acc[3], a, bt1[2], bt1[3]);
        }

        if (kt < ID / 32 - 1) {
            const int nxt = cur ^ 1;
            unsigned lo = btous(pa.x) | ((unsigned)btous(pa.y) << 16);
            unsigned hi = btous(pa.z) | ((unsigned)btous(pa.w) << 16);
            *(uint2*)&sA[nxt][arow * ASTR + ac4] = make_uint2(lo, hi);
            *(uint4*)&sB[nxt][brow * BSTR + bcol] = pb;
        }
        __syncthreads();
    }

    #pragma unroll
    for (int nt = 0; nt < 4; ++nt) {
        long m  = m0 + wy * 16 + gid;
        int  cc = n0 + wx * 32 + nt * 8 + tig * 2;
        float b0 = g_biasI[cc], b1 = g_biasI[cc + 1];
        *(float2*)&g_xw[m * G4 + cc] =
            make_float2(acc[nt][0] + b0, acc[nt][1] + b1);
        *(float2*)&g_xw[(m + 8) * G4 + cc] =
            make_float2(acc[nt][2] + b0, acc[nt][3] + b1);
    }
}

// ---------------- serial step: gates = h @ Wh (+xw), fused LSTM update (bf16) -------
// grid (32,4) x 512 threads; tile 64x128; K=1024 in EIGHT 128-wide k-tiles
// (8 barriers/step instead of 32; mma block per tile now covers prefetch latency).
__global__ __launch_bounds__(512) void gemm_step(const int* __restrict__ lengths, int t) {
    extern __shared__ __align__(16) unsigned short smn[];
    unsigned short* sA = smn;                    // 2 x 64 x 136
    unsigned short* sB = smn + 2 * STEP_ASZ;     // 2 x 128 x 136

    const unsigned short* __restrict__ hin  = g_hbf[t & 1];
    unsigned short*       __restrict__ hout = g_hbf[(t + 1) & 1];

    const int tid = threadIdx.x;
    const int warp = tid >> 5, lane = tid & 31;
    const int gid = lane >> 2, tig = lane & 3;
    const int wy = warp >> 2, wx = warp & 3;
    const int m0 = blockIdx.y * 64, n0 = blockIdx.x * 128;

    // staging: A 64x128 (2 uint4/thread), B 128x128 (4 uint4/thread)
    const int arow = tid >> 3, ac = (tid & 7) * 16;   // 8 thr x 16 elems = 128 k
    const int brow = tid >> 2, bcol = (tid & 3) * 32; // 4 thr x 32 elems = 128 n

    const int aoff = (wy * 16 + (lane & 15)) * BSTR + (lane >> 4) * 8;
    const int boff = (lane & 15) * BSTR + wx * 32 + (lane >> 4) * 8;

    uint4 pa0, pa1, pb[4];
    pa0 = *(const uint4*)(hin + (m0 + arow) * HD + ac);
    pa1 = *(const uint4*)(hin + (m0 + arow) * HD + ac + 8);
    #pragma unroll
    for (int i = 0; i < 4; ++i)
        pb[i] = *(const uint4*)(g_Whb + (long)brow * G4 + n0 + bcol + i * 8);

    *(uint4*)&sA[arow * BSTR + ac]     = pa0;
    *(uint4*)&sA[arow * BSTR + ac + 8] = pa1;
    #pragma unroll
    for (int i = 0; i < 4; ++i)
        *(uint4*)&sB[brow * BSTR + bcol + i * 8] = pb[i];
    __syncthreads();

    float acc[4][4] = {};

    for (int kt = 0; kt < HD / 128; ++kt) {
        const int cur = kt & 1;
        const unsigned short* cA = sA + cur * STEP_ASZ;
        const unsigned short* cB = sB + cur * STEP_BSZ;

        if (kt < HD / 128 - 1) {
            const int kb = (kt + 1) * 128;
            pa0 = *(const uint4*)(hin + (m0 + arow) * HD + kb + ac);
            pa1 = *(const uint4*)(hin + (m0 + arow) * HD + kb + ac + 8);
            #pragma unroll
            for (int i = 0; i < 4; ++i)
                pb[i] = *(const uint4*)(g_Whb + (long)(kb + brow) * G4 + n0 + bcol + i * 8);
        }

        #pragma unroll
        for (int ks = 0; ks < 8; ++ks) {
            unsigned a[4], bt0[4], bt1[4];
            ldsm_x4 (a,   cA + aoff + ks * 16);
            ldsm_x4t(bt0, cB + ks * 16 * BSTR + boff);
            ldsm_x4t(bt1, cB + ks * 16 * BSTR + boff + 16);
            mma_bf16(acc[0], a, bt0[0], bt0[1]);
            mma_bf16(acc[1], a, bt0[2], bt0[3]);
            mma_bf16(acc[2], a, bt1[0], bt1[1]);
            mma_bf16(acc[3], a, bt1[2], bt1[3]);
        }

        if (kt < HD / 128 - 1) {
            unsigned short* nA = sA + (cur ^ 1) * STEP_ASZ;
            unsigned short* nB = sB + (cur ^ 1) * STEP_BSZ;
            *(uint4*)&nA[arow * BSTR + ac]     = pa0;
            *(uint4*)&nA[arow * BSTR + ac + 8] = pa1;
            #pragma unroll
            for (int i = 0; i < 4; ++i)
                *(uint4*)&nB[brow * BSTR + bcol + i * 8] = pb[i];
        }
        __syncthreads();
    }

    // register-shuffle epilogue: lane pair (tig, tig^1) assembles (i,f,g,o) quadruples
    const int odd = tig & 1;
    const int p = m0 + wy * 16 + gid + (odd ? 8 : 0);
    const int len1 = lengths[p] - 1;
    const float* xrow = g_xw + ((long)t * PN + p) * G4;

    #pragma unroll
    for (int nt = 0; nt < 4; ++nt) {
        float e0 = __shfl_xor_sync(0xffffffffu, acc[nt][0], 1);
        float e1 = __shfl_xor_sync(0xffffffffu, acc[nt][1], 1);
        float e2 = __shfl_xor_sync(0xffffffffu, acc[nt][2], 1);
        float e3 = __shfl_xor_sync(0xffffffffu, acc[nt][3], 1);
        float gi = odd ? e2 : acc[nt][0];
        float gf = odd ? e3 : acc[nt][1];
        float gg = odd ? acc[nt][2] : e0;
        float go = odd ? acc[nt][3] : e1;
        int j4 = n0 + wx * 32 + nt * 8 + ((tig & 2) << 1);
        float4 xw = *(const float4*)(xrow + j4);
        int cidx = p * HD + (j4 >> 2);
        float c = g_c[cidx];
        c = sigf(gf + xw.y) * c + sigf(gi + xw.x) * tanhf(gg + xw.z);
        float h = sigf(go + xw.w) * tanhf(c);
        g_c[cidx] = c;
        hout[cidx] = btous(h);
        if (t == len1) g_fh[cidx] = h;
    }
}

// ---------------- head GEMM (tf32, unchanged) ----------------
__global__ __launch_bounds__(256) void gemm_head(int mode, const float* __restrict__ bias) {
    __shared__ unsigned sA[64][36];
    __shared__ unsigned sB[32][132];

    const float*    A  = mode ? g_v   : g_fh;
    const unsigned* Bt = mode ? g_WoT : g_WvT;
    float*          C  = mode ? g_attn : g_v;

    const int tid = threadIdx.x;
    const int warp = tid >> 5, lane = tid & 31;
    const int gid = lane >> 2, tig = lane & 3;
    const int wy = warp >> 2, wx = warp & 3;
    const int m0 = blockIdx.y * 64, n0 = blockIdx.x * 128;

    float acc[2][4][4] = {};

    for (int kt = 0; kt < HD / 32; ++kt) {
        const int kb = kt * 32;
        #pragma unroll
        for (int i = 0; i < 2; ++i) {
            int f4 = tid * 2 + i;
            int r = f4 >> 3, c = (f4 & 7) << 2;
            float4 v = *(const float4*)(A + (m0 + r) * HD + kb + c);
            sA[r][c] = f2tf(v.x); sA[r][c + 1] = f2tf(v.y);
            sA[r][c + 2] = f2tf(v.z); sA[r][c + 3] = f2tf(v.w);
        }
        #pragma unroll
        for (int i = 0; i < 4; ++i) {
            int f4 = tid * 4 + i;
            int r = f4 >> 5, c = (f4 & 31) << 2;
            *(uint4*)&sB[r][c] = *(const uint4*)(Bt + (long)(kb + r) * HD + n0 + c);
        }
        __syncthreads();

        #pragma unroll
        for (int ks = 0; ks < 4; ++ks) {
            unsigned a[2][4], b[4][2];
            #pragma unroll
            for (int mt = 0; mt < 2; ++mt) {
                int r = wy * 32 + mt * 16 + gid;
                a[mt][0] = sA[r][ks * 8 + tig];
                a[mt][1] = sA[r + 8][ks * 8 + tig];
                a[mt][2] = sA[r][ks * 8 + tig + 4];
                a[mt][3] = sA[r + 8][ks * 8 + tig + 4];
            }
            #pragma unroll
            for (int nt = 0; nt < 4; ++nt) {
                int cc = wx * 32 + nt * 8 + gid;
                b[nt][0] = sB[ks * 8 + tig][cc];
                b[nt][1] = sB[ks * 8 + tig + 4][cc];
            }
            #pragma unroll
            for (int mt = 0; mt < 2; ++mt)
                #pragma unroll
                for (int nt = 0; nt < 4; ++nt)
                    mma_tf32(acc[mt][nt], a[mt][0], a[mt][1], a[mt][2], a[mt][3],
                             b[nt][0], b[nt][1]);
        }
        __syncthreads();
    }

    #pragma unroll
    for (int mt = 0; mt < 2; ++mt) {
        #pragma unroll
        for (int nt = 0; nt < 4; ++nt) {
            int r  = m0 + wy * 32 + mt * 16 + gid;
            int cc = n0 + wx * 32 + nt * 8 + tig * 2;
            C[r * HD + cc]           = acc[mt][nt][0] + bias[cc];
            C[r * HD + cc + 1]       = acc[mt][nt][1] + bias[cc + 1];
            C[(r + 8) * HD + cc]     = acc[mt][nt][2] + bias[cc];
            C[(r + 8) * HD + cc + 1] = acc[mt][nt][3] + bias[cc + 1];
        }
    }
}

// ---------------- pool + final ----------------
__global__ void pool_max() {
    int j = blockIdx.x * blockDim.x + threadIdx.x;
    float m = -3.4e38f;
    for (int p = 0; p < PN; ++p) m = fmaxf(m, g_attn[p * HD + j]);
    g_pool[j] = m;
}

__global__ void final_out(const float* __restrict__ Wlin, const float* __restrict__ blin,
                          float* __restrict__ out) {
    __shared__ float s0[256], s1[256];
    int tid = threadIdx.x;
    float a0 = 0.0f, a1 = 0.0f;
    for (int j = tid; j < HD; j += 256) {
        float pv = g_pool[j];
        a0 += pv * Wlin[j];
        a1 += pv * Wlin[HD + j];
    }
    s0[tid] = a0; s1[tid] = a1;
    __syncthreads();
    for (int s = 128; s > 0; s >>= 1) {
        if (tid < s) { s0[tid] += s0[tid + s]; s1[tid] += s1[tid + s]; }
        __syncthreads();
    }
    if (tid == 0) {
        out[0] = 1.0f / (1.0f + expf(-(s0[0] + blin[0])));
        out[1] = 1.0f / (1.0f + expf(-(s1[0] + blin[1])));
    }
}

// ---------------- launch ----------------
extern "C" void kernel_launch(void* const* d_in, const int* in_sizes, int n_in,
                              void* d_out, int out_size) {
    const int*   paths   = (const int*)d_in[0];
    const int*   lengths = (const int*)d_in[1];
    const float* emb     = (const float*)d_in[2];
    const float* Wih     = (const float*)d_in[3];
    const float* Whh     = (const float*)d_in[4];
    const float* bih     = (const float*)d_in[5];
    const float* bhh     = (const float*)d_in[6];
    const float* Win     = (const float*)d_in[7];
    const float* bin     = (const float*)d_in[8];
    const float* Wout    = (const float*)d_in[9];
    const float* bout    = (const float*)d_in[10];
    const float* Wlin    = (const float*)d_in[11];
    const float* blin    = (const float*)d_in[12];
    float* out = (float*)d_out;

    // >48KB dynamic smem; idempotent host call (not an allocation), graph-safe.
    cudaFuncSetAttribute(gemm_step, cudaFuncAttributeMaxDynamicSharedMemorySize, SMEM_STEP);

    prep_w<<<6160, 256>>>(Wih, Whh, bih, bhh);
    prep_rest<<<2080, 256>>>(Win, Wout);

    gemm_xw<<<dim3(32, 256), 512>>>(emb, paths);   // all-timestep input projection (bf16)

    for (int t = 0; t < LN; ++t)
        gemm_step<<<dim3(32, 4), 512, SMEM_STEP>>>(lengths, t);  // fused bf16 GEMM + LSTM

    gemm_head<<<dim3(8, 4), 256>>>(0, bin + 2 * HD);   // v = fh @ Wv^T + b_v
    gemm_head<<<dim3(8, 4), 256>>>(1, bout);           // attn = v @ Wout^T + b_out
    pool_max<<<4, 256>>>();
    final_out<<<1, 256>>>(Wlin, blin, out);
}

// round 15
// speedup vs baseline: 1.3652x; 1.3652x over previous
#include <cuda_runtime.h>
#include <cuda_bf16.h>
#include <math.h>

#define PN 256      // paths
#define LN 64       // max length
#define ID 512      // input dim
#define HD 1024     // hidden
#define G4 4096     // 4*HD
#define ASTR 40     // A smem row stride (bf16 elems), conflict-free for ldmatrix
#define BSTR 136    // B smem row stride (bf16 elems), conflict-free for ldmatrix.trans

// ---------------- scratch (__device__ globals) ----------------
// Interleaved gate layout: column n = 4*j + g, g in {i,f,g,o}
__device__ __align__(16) unsigned short g_Whb[HD * G4];  // W_hh bf16 k-major interleaved (8MB)
__device__ __align__(16) unsigned short g_Wib[ID * G4];  // W_ih bf16 k-major interleaved (4MB)
__device__ float    g_biasI[G4];                          // (b_ih+b_hh) interleaved
__device__ float    g_xw[(long)LN * PN * G4];             // x_t@W_ih^T + b (256MB)
__device__ __align__(16) unsigned short g_hbf[2][PN * HD]; // h bf16, double-buffered
__device__ float    g_c[PN * HD];
__device__ float    g_fh[PN * HD];                        // final hidden (fp32, for head)
__device__ unsigned g_WvT[HD * HD];                       // W_v k-major tf32
__device__ unsigned g_WoT[HD * HD];                       // W_out k-major tf32
__device__ float    g_v[PN * HD];
__device__ float    g_attn[PN * HD];
__device__ float    g_pool[HD];

// ---------------- helpers ----------------
__device__ __forceinline__ unsigned f2tf(float x) {
    unsigned r;
    asm("cvt.rna.tf32.f32 %0, %1;" : "=r"(r) : "f"(x));
    return r;
}
__device__ __forceinline__ unsigned short btous(float x) {
    return __bfloat16_as_ushort(__float2bfloat16_rn(x));
}
__device__ __forceinline__ float sigf(float x) { return 1.0f / (1.0f + expf(-x)); }

// fast epilogue math: MUFU-based, ~1e-6 rel err (bf16 noise floor is ~4e-3)
__device__ __forceinline__ float fsig(float x) {
    return __fdividef(1.0f, 1.0f + __expf(-x));
}
__device__ __forceinline__ float ftanh(float x) {
    return 1.0f - __fdividef(2.0f, __expf(2.0f * x) + 1.0f);
}

__device__ __forceinline__ void mma_tf32(float c[4],
                                         unsigned a0, unsigned a1, unsigned a2, unsigned a3,
                                         unsigned b0, unsigned b1) {
    asm volatile(
        "mma.sync.aligned.m16n8k8.row.col.f32.tf32.tf32.f32 "
        "{%0,%1,%2,%3},{%4,%5,%6,%7},{%8,%9},{%0,%1,%2,%3};"
        : "+f"(c[0]), "+f"(c[1]), "+f"(c[2]), "+f"(c[3])
        : "r"(a0), "r"(a1), "r"(a2), "r"(a3), "r"(b0), "r"(b1));
}

__device__ __forceinline__ void mma_bf16(float c[4], const unsigned a[4],
                                         unsigned b0, unsigned b1) {
    asm volatile(
        "mma.sync.aligned.m16n8k16.row.col.f32.bf16.bf16.f32 "
        "{%0,%1,%2,%3},{%4,%5,%6,%7},{%8,%9},{%0,%1,%2,%3};"
        : "+f"(c[0]), "+f"(c[1]), "+f"(c[2]), "+f"(c[3])
        : "r"(a[0]), "r"(a[1]), "r"(a[2]), "r"(a[3]), "r"(b0), "r"(b1));
}

__device__ __forceinline__ void ldsm_x4(unsigned r[4], const void* p) {
    unsigned a = (unsigned)__cvta_generic_to_shared(p);
    asm volatile("ldmatrix.sync.aligned.m8n8.x4.shared.b16 {%0,%1,%2,%3}, [%4];"
        : "=r"(r[0]), "=r"(r[1]), "=r"(r[2]), "=r"(r[3]) : "r"(a));
}
__device__ __forceinline__ void ldsm_x4t(unsigned r[4], const void* p) {
    unsigned a = (unsigned)__cvta_generic_to_shared(p);
    asm volatile("ldmatrix.sync.aligned.m8n8.x4.trans.shared.b16 {%0,%1,%2,%3}, [%4];"
        : "=r"(r[0]), "=r"(r[1]), "=r"(r[2]), "=r"(r[3]) : "r"(a));
}

// ---------------- prep ----------------
__global__ void prep_w(const float* __restrict__ Wih, const float* __restrict__ Whh,
                       const float* __restrict__ bih, const float* __restrict__ bhh) {
    const int total = (ID + HD) * G4 + G4;
    for (int e = blockIdx.x * blockDim.x + threadIdx.x; e < total; e += gridDim.x * blockDim.x) {
        if (e < ID * G4) {
            int k = e >> 12, n = e & 4095;
            int j = n >> 2, g = n & 3;
            g_Wib[e] = btous(Wih[(g * HD + j) * ID + k]);
        } else if (e < (ID + HD) * G4) {
            int e2 = e - ID * G4;
            int k = e2 >> 12, n = e2 & 4095;
            int j = n >> 2, g = n & 3;
            g_Whb[e2] = btous(Whh[(g * HD + j) * HD + k]);
        } else {
            int n = e - (ID + HD) * G4;
            int j = n >> 2, g = n & 3;
            g_biasI[n] = bih[g * HD + j] + bhh[g * HD + j];
        }
    }
}

__global__ void prep_rest(const float* __restrict__ Win, const float* __restrict__ Wout) {
    const int HH = HD * HD;
    const int total = 2 * HH + 2 * PN * HD;
    for (int e = blockIdx.x * blockDim.x + threadIdx.x; e < total; e += gridDim.x * blockDim.x) {
        if (e < HH) {
            int k = e >> 10, n = e & 1023;
            g_WvT[e] = f2tf(Win[(2 * HD + n) * HD + k]);
        } else if (e < 2 * HH) {
            int e2 = e - HH;
            int k = e2 >> 10, n = e2 & 1023;
            g_WoT[e2] = f2tf(Wout[n * HD + k]);
        } else {
            int i = e - 2 * HH;
            if (i < PN * HD) g_hbf[0][i] = 0; else g_c[i - PN * HD] = 0.0f;
        }
    }
}

// ---------------- xw precompute GEMM (bf16, unchanged from R13) ----------------
__global__ __launch_bounds__(512) void gemm_xw(const float* __restrict__ emb,
                                               const int* __restrict__ paths) {
    __shared__ __align__(16) unsigned short sA[2][64 * ASTR];
    __shared__ __align__(16) unsigned short sB[2][32 * BSTR];

    const int tid = threadIdx.x;
    const int warp = tid >> 5, lane = tid & 31;
    const int gid = lane >> 2, tig = lane & 3;
    const int wy = warp >> 2, wx = warp & 3;
    const int m0 = blockIdx.y * 64, n0 = blockIdx.x * 128;
    const int tt = m0 >> 8, p0 = m0 & 255;

    const int arow = tid >> 3, ac4 = (tid & 7) * 4;
    const int brow = tid >> 4, bcol = (tid & 15) * 8;

    const long abase = (long)paths[(p0 + arow) * LN + tt] * ID + ac4;

    const int aoff = (wy * 16 + (lane & 15)) * ASTR + (lane >> 4) * 8;
    const int boff = (lane & 15) * BSTR + wx * 32 + (lane >> 4) * 8;

    float4 pa = *(const float4*)(emb + abase);
    uint4  pb = *(const uint4*)(g_Wib + (long)brow * G4 + n0 + bcol);

    {
        unsigned lo = btous(pa.x) | ((unsigned)btous(pa.y) << 16);
        unsigned hi = btous(pa.z) | ((unsigned)btous(pa.w) << 16);
        *(uint2*)&sA[0][arow * ASTR + ac4] = make_uint2(lo, hi);
        *(uint4*)&sB[0][brow * BSTR + bcol] = pb;
    }
    __syncthreads();

    float acc[4][4] = {};

    for (int kt = 0; kt < ID / 32; ++kt) {
        const int cur = kt & 1;
        if (kt < ID / 32 - 1) {
            const int kb = (kt + 1) * 32;
            pa = *(const float4*)(emb + abase + kb);
            pb = *(const uint4*)(g_Wib + (long)(kb + brow) * G4 + n0 + bcol);
        }

        #pragma unroll
        for (int ks = 0; ks < 2; ++ks) {
            unsigned a[4], bt0[4], bt1[4];
            ldsm_x4 (a,   &sA[cur][aoff + ks * 16]);
            ldsm_x4t(bt0, &sB[cur][ks * 16 * BSTR + boff]);
            ldsm_x4t(bt1, &sB[cur][ks * 16 * BSTR + boff + 16]);
            mma_bf16(acc[0], a, bt0[0], bt0[1]);
            mma_bf16(acc[1], a, bt0[2], bt0[3]);
            mma_bf16(acc[2], a, bt1[0], bt1[1]);
            mma_bf16(acc[3], a, bt1[2], bt1[3]);
        }

        if (kt < ID / 32 - 1) {
            const int nxt = cur ^ 1;
            unsigned lo = btous(pa.x) | ((unsigned)btous(pa.y) << 16);
            unsigned hi = btous(pa.z) | ((unsigned)btous(pa.w) << 16);
            *(uint2*)&sA[nxt][arow * ASTR + ac4] = make_uint2(lo, hi);
            *(uint4*)&sB[nxt][brow * BSTR + bcol] = pb;
        }
        __syncthreads();
    }

    #pragma unroll
    for (int nt = 0; nt < 4; ++nt) {
        long m  = m0 + wy * 16 + gid;
        int  cc = n0 + wx * 32 + nt * 8 + tig * 2;
        float b0 = g_biasI[cc], b1 = g_biasI[cc + 1];
        *(float2*)&g_xw[m * G4 + cc] =
            make_float2(acc[nt][0] + b0, acc[nt][1] + b1);
        *(float2*)&g_xw[(m + 8) * G4 + cc] =
            make_float2(acc[nt][2] + b0, acc[nt][3] + b1);
    }
}

// ---------------- serial step: gates = h @ Wh (+xw), fused LSTM update (bf16) -------
// grid (32,4) x 512 threads; tile 64x128, K=1024, kt=32 (R13 config).
// NEW: epilogue inputs (xw, c, lengths) prefetched into registers at kernel entry
// so their DRAM latency overlaps the GEMM; epilogue uses MUFU-based fast math.
__global__ __launch_bounds__(512) void gemm_step(const int* __restrict__ lengths, int t) {
    __shared__ __align__(16) unsigned short sA[2][64 * ASTR];
    __shared__ __align__(16) unsigned short sB[2][32 * BSTR];

    const unsigned short* __restrict__ hin  = g_hbf[t & 1];
    unsigned short*       __restrict__ hout = g_hbf[(t + 1) & 1];

    const int tid = threadIdx.x;
    const int warp = tid >> 5, lane = tid & 31;
    const int gid = lane >> 2, tig = lane & 3;
    const int wy = warp >> 2, wx = warp & 3;
    const int m0 = blockIdx.y * 64, n0 = blockIdx.x * 128;

    // ---- epilogue operand prefetch (overlaps entire GEMM) ----
    const int odd = tig & 1;
    const int p = m0 + wy * 16 + gid + (odd ? 8 : 0);
    const int len1 = lengths[p] - 1;
    const float* xrow = g_xw + ((long)t * PN + p) * G4;
    float4 xwv[4];
    float  cv[4];
    int    cidx[4];
    #pragma unroll
    for (int nt = 0; nt < 4; ++nt) {
        int j4 = n0 + wx * 32 + nt * 8 + ((tig & 2) << 1);
        xwv[nt] = *(const float4*)(xrow + j4);
        cidx[nt] = p * HD + (j4 >> 2);
        cv[nt] = g_c[cidx[nt]];
    }

    const int arow = tid >> 3, ac4 = (tid & 7) * 4;   // A stage: 8B
    const int brow = tid >> 4, bcol = (tid & 15) * 8; // B stage: 16B

    const int aoff = (wy * 16 + (lane & 15)) * ASTR + (lane >> 4) * 8;
    const int boff = (lane & 15) * BSTR + wx * 32 + (lane >> 4) * 8;

    uint2 pa = *(const uint2*)(hin + (m0 + arow) * HD + ac4);
    uint4 pb = *(const uint4*)(g_Whb + (long)brow * G4 + n0 + bcol);

    *(uint2*)&sA[0][arow * ASTR + ac4] = pa;
    *(uint4*)&sB[0][brow * BSTR + bcol] = pb;
    __syncthreads();

    float acc[4][4] = {};

    for (int kt = 0; kt < HD / 32; ++kt) {
        const int cur = kt & 1;
        if (kt < HD / 32 - 1) {
            const int kb = (kt + 1) * 32;
            pa = *(const uint2*)(hin + (m0 + arow) * HD + kb + ac4);
            pb = *(const uint4*)(g_Whb + (long)(kb + brow) * G4 + n0 + bcol);
        }

        #pragma unroll
        for (int ks = 0; ks < 2; ++ks) {
            unsigned a[4], bt0[4], bt1[4];
            ldsm_x4 (a,   &sA[cur][aoff + ks * 16]);
            ldsm_x4t(bt0, &sB[cur][ks * 16 * BSTR + boff]);
            ldsm_x4t(bt1, &sB[cur][ks * 16 * BSTR + boff + 16]);
            mma_bf16(acc[0], a, bt0[0], bt0[1]);
            mma_bf16(acc[1], a, bt0[2], bt0[3]);
            mma_bf16(acc[2], a, bt1[0], bt1[1]);
            mma_bf16(acc[3], a, bt1[2], bt1[3]);
        }

        if (kt < HD / 32 - 1) {
            const int nxt = cur ^ 1;
            *(uint2*)&sA[nxt][arow * ASTR + ac4] = pa;
            *(uint4*)&sB[nxt][brow * BSTR + bcol] = pb;
        }
        __syncthreads();
    }

    // register-shuffle epilogue: lane pair (tig, tig^1) assembles (i,f,g,o) quadruples
    #pragma unroll
    for (int nt = 0; nt < 4; ++nt) {
        float e0 = __shfl_xor_sync(0xffffffffu, acc[nt][0], 1);
        float e1 = __shfl_xor_sync(0xffffffffu, acc[nt][1], 1);
        float e2 = __shfl_xor_sync(0xffffffffu, acc[nt][2], 1);
        float e3 = __shfl_xor_sync(0xffffffffu, acc[nt][3], 1);
        float gi = odd ? e2 : acc[nt][0];
        float gf = odd ? e3 : acc[nt][1];
        float gg = odd ? acc[nt][2] : e0;
        float go = odd ? acc[nt][3] : e1;
        float c = cv[nt];
        c = fsig(gf + xwv[nt].y) * c + fsig(gi + xwv[nt].x) * ftanh(gg + xwv[nt].z);
        float h = fsig(go + xwv[nt].w) * ftanh(c);
        g_c[cidx[nt]] = c;
        hout[cidx[nt]] = btous(h);
        if (t == len1) g_fh[cidx[nt]] = h;
    }
}

// ---------------- head GEMM (tf32, unchanged) ----------------
__global__ __launch_bounds__(256) void gemm_head(int mode, const float* __restrict__ bias) {
    __shared__ unsigned sA[64][36];
    __shared__ unsigned sB[32][132];

    const float*    A  = mode ? g_v   : g_fh;
    const unsigned* Bt = mode ? g_WoT : g_WvT;
    float*          C  = mode ? g_attn : g_v;

    const int tid = threadIdx.x;
    const int warp = tid >> 5, lane = tid & 31;
    const int gid = lane >> 2, tig = lane & 3;
    const int wy = warp >> 2, wx = warp & 3;
    const int m0 = blockIdx.y * 64, n0 = blockIdx.x * 128;

    float acc[2][4][4] = {};

    for (int kt = 0; kt < HD / 32; ++kt) {
        const int kb = kt * 32;
        #pragma unroll
        for (int i = 0; i < 2; ++i) {
            int f4 = tid * 2 + i;
            int r = f4 >> 3, c = (f4 & 7) << 2;
            float4 v = *(const float4*)(A + (m0 + r) * HD + kb + c);
            sA[r][c] = f2tf(v.x); sA[r][c + 1] = f2tf(v.y);
            sA[r][c + 2] = f2tf(v.z); sA[r][c + 3] = f2tf(v.w);
        }
        #pragma unroll
        for (int i = 0; i < 4; ++i) {
            int f4 = tid * 4 + i;
            int r = f4 >> 5, c = (f4 & 31) << 2;
            *(uint4*)&sB[r][c] = *(const uint4*)(Bt + (long)(kb + r) * HD + n0 + c);
        }
        __syncthreads();

        #pragma unroll
        for (int ks = 0; ks < 4; ++ks) {
            unsigned a[2][4], b[4][2];
            #pragma unroll
            for (int mt = 0; mt < 2; ++mt) {
                int r = wy * 32 + mt * 16 + gid;
                a[mt][0] = sA[r][ks * 8 + tig];
                a[mt][1] = sA[r + 8][ks * 8 + tig];
                a[mt][2] = sA[r][ks * 8 + tig + 4];
                a[mt][3] = sA[r + 8][ks * 8 + tig + 4];
            }
            #pragma unroll
            for (int nt = 0; nt < 4; ++nt) {
                int cc = wx * 32 + nt * 8 + gid;
                b[nt][0] = sB[ks * 8 + tig][cc];
                b[nt][1] = sB[ks * 8 + tig + 4][cc];
            }
            #pragma unroll
            for (int mt = 0; mt < 2; ++mt)
                #pragma unroll
                for (int nt = 0; nt < 4; ++nt)
                    mma_tf32(acc[mt][nt], a[mt][0], a[mt][1], a[mt][2], a[mt][3],
                             b[nt][0], b[nt][1]);
        }
        __syncthreads();
    }

    #pragma unroll
    for (int mt = 0; mt < 2; ++mt) {
        #pragma unroll
        for (int nt = 0; nt < 4; ++nt) {
            int r  = m0 + wy * 32 + mt * 16 + gid;
            int cc = n0 + wx * 32 + nt * 8 + tig * 2;
            C[r * HD + cc]           = acc[mt][nt][0] + bias[cc];
            C[r * HD + cc + 1]       = acc[mt][nt][1] + bias[cc + 1];
            C[(r + 8) * HD + cc]     = acc[mt][nt][2] + bias[cc];
            C[(r + 8) * HD + cc + 1] = acc[mt][nt][3] + bias[cc + 1];
        }
    }
}

// ---------------- pool + final ----------------
__global__ void pool_max() {
    int j = blockIdx.x * blockDim.x + threadIdx.x;
    float m = -3.4e38f;
    for (int p = 0; p < PN; ++p) m = fmaxf(m, g_attn[p * HD + j]);
    g_pool[j] = m;
}

__global__ void final_out(const float* __restrict__ Wlin, const float* __restrict__ blin,
                          float* __restrict__ out) {
    __shared__ float s0[256], s1[256];
    int tid = threadIdx.x;
    float a0 = 0.0f, a1 = 0.0f;
    for (int j = tid; j < HD; j += 256) {
        float pv = g_pool[j];
        a0 += pv * Wlin[j];
        a1 += pv * Wlin[HD + j];
    }
    s0[tid] = a0; s1[tid] = a1;
    __syncthreads();
    for (int s = 128; s > 0; s >>= 1) {
        if (tid < s) { s0[tid] += s0[tid + s]; s1[tid] += s1[tid + s]; }
        __syncthreads();
    }
    if (tid == 0) {
        out[0] = 1.0f / (1.0f + expf(-(s0[0] + blin[0])));
        out[1] = 1.0f / (1.0f + expf(-(s1[0] + blin[1])));
    }
}

// ---------------- launch ----------------
extern "C" void kernel_launch(void* const* d_in, const int* in_sizes, int n_in,
                              void* d_out, int out_size) {
    const int*   paths   = (const int*)d_in[0];
    const int*   lengths = (const int*)d_in[1];
    const float* emb     = (const float*)d_in[2];
    const float* Wih     = (const float*)d_in[3];
    const float* Whh     = (const float*)d_in[4];
    const float* bih     = (const float*)d_in[5];
    const float* bhh     = (const float*)d_in[6];
    const float* Win     = (const float*)d_in[7];
    const float* bin     = (const float*)d_in[8];
    const float* Wout    = (const float*)d_in[9];
    const float* bout    = (const float*)d_in[10];
    const float* Wlin    = (const float*)d_in[11];
    const float* blin    = (const float*)d_in[12];
    float* out = (float*)d_out;

    prep_w<<<6160, 256>>>(Wih, Whh, bih, bhh);
    prep_rest<<<2080, 256>>>(Win, Wout);

    gemm_xw<<<dim3(32, 256), 512>>>(emb, paths);   // all-timestep input projection (bf16)

    for (int t = 0; t < LN; ++t)
        gemm_step<<<dim3(32, 4), 512>>>(lengths, t);   // fused bf16 GEMM + LSTM update

    gemm_head<<<dim3(8, 4), 256>>>(0, bin + 2 * HD);   // v = fh @ Wv^T + b_v
    gemm_head<<<dim3(8, 4), 256>>>(1, bout);           // attn = v @ Wout^T + b_out
    pool_max<<<4, 256>>>();
    final_out<<<1, 256>>>(Wlin, blin, out);
}